// round 1
// baseline (speedup 1.0000x reference)
#include <cuda_runtime.h>
#include <math.h>

#define T_LEN   65536
#define HID     256
#define INP     80          // IN_DIM = 72, padded to 80 for clean BK=16 tiling
#define IN_RAW  72
#define NOUT    1024        // 4 * HID stacked weight rows (interleaved per channel)
#define CHUNK   256
#define NCH     (T_LEN / CHUNK)   // 256

// ---------------- scratch (device globals: allocation-free) ----------------
static __device__ float g_x   [T_LEN * INP];   // padded concat input
static __device__ float g_abar[T_LEN * HID];
static __device__ float g_bx  [T_LEN * HID];
static __device__ float g_c   [T_LEN * HID];
static __device__ float g_y0  [T_LEN * HID];   // layer 0 output
static __device__ float g_y1  [T_LEN * HID];   // layer 1 output
static __device__ float g_P   [NCH * HID];
static __device__ float g_S   [NCH * HID];
static __device__ float g_H0  [NCH * HID];
static __device__ float g_W0p [NOUT * INP];    // layer0 weights, interleaved+padded
static __device__ float g_W1p [NOUT * HID];    // layer1 weights, interleaved
static __device__ float g_negA[2 * HID];       // -exp(Alog) per layer

// ---------------- weight prep ----------------
// Row r = 4*h + j  (j: 0=Win, 1=WB, 2=WC, 3=Wd), K columns (pad with 0).
__global__ void prep_w0_kernel(const float* __restrict__ Win,
                               const float* __restrict__ WB,
                               const float* __restrict__ WC,
                               const float* __restrict__ Wd) {
    int idx = blockIdx.x * 256 + threadIdx.x;           // NOUT*INP total
    int r = idx / INP, k = idx % INP;
    int h = r >> 2, j = r & 3;
    float v = 0.f;
    if (k < IN_RAW) {
        const float* src = (j == 0) ? Win : (j == 1) ? WB : (j == 2) ? WC : Wd;
        v = src[h * IN_RAW + k];
    }
    g_W0p[idx] = v;
}

__global__ void prep_w1_kernel(const float* __restrict__ Win,
                               const float* __restrict__ WB,
                               const float* __restrict__ WC,
                               const float* __restrict__ Wd) {
    int idx = blockIdx.x * 256 + threadIdx.x;           // NOUT*HID total
    int r = idx / HID, k = idx % HID;
    int h = r >> 2, j = r & 3;
    const float* src = (j == 0) ? Win : (j == 1) ? WB : (j == 2) ? WC : Wd;
    g_W1p[idx] = src[h * HID + k];
}

__global__ void prep_a_kernel(const float* __restrict__ Alog0,
                              const float* __restrict__ Alog1) {
    int h = threadIdx.x;
    g_negA[h]       = -expf(Alog0[h]);
    g_negA[HID + h] = -expf(Alog1[h]);
}

// ---------------- input build: x = [obs | emb[actions] | 0-pad] ----------------
__global__ void build_x_kernel(const float* __restrict__ obs,
                               const int* __restrict__ act,
                               const float* __restrict__ emb) {
    int idx = blockIdx.x * 256 + threadIdx.x;           // T_LEN*INP total
    int t = idx / INP, k = idx % INP;
    float v;
    if (k < 64)       v = obs[t * 64 + k];
    else if (k < 72)  v = emb[act[t] * 8 + (k - 64)];
    else              v = 0.f;
    g_x[idx] = v;
}

// ---------------- fused GEMM + SSM-gate epilogue ----------------
// out[m, n] = sum_k A[m,k] * W[n,k];  W rows interleaved so a thread's 4
// consecutive n = one channel's (x_state, B, C, d). Epilogue writes
// abar = exp(sigmoid(d) * negA[h]), bx = B*x_state, c = C.
// Tile: BM=128, BN=64, BK=16, 256 threads, 8x4 microtile.
template <int LAYER>
__global__ void __launch_bounds__(256) gemm_fused_kernel() {
    constexpr int K = (LAYER == 0) ? INP : HID;
    const float* __restrict__ A = (LAYER == 0) ? g_x : g_y0;
    const float* __restrict__ W = (LAYER == 0) ? g_W0p : g_W1p;

    __shared__ __align__(16) float As[16][132];
    __shared__ __align__(16) float Ws[16][68];

    const int tid = threadIdx.x;
    const int tx = tid & 15;          // 16 -> 64 n (16 channels)
    const int ty = tid >> 4;          // 16 -> 128 m
    const int m0 = blockIdx.y * 128;
    const int n0 = blockIdx.x * 64;

    float acc[8][4];
#pragma unroll
    for (int i = 0; i < 8; i++)
#pragma unroll
        for (int j = 0; j < 4; j++) acc[i][j] = 0.f;

    for (int k0 = 0; k0 < K; k0 += 16) {
        // load A tile (128 x 16) transposed into As[k][m]
#pragma unroll
        for (int l = 0; l < 2; l++) {
            int idx = tid + l * 256;
            int m  = idx >> 2;
            int kg = (idx & 3) * 4;
            float4 v = *reinterpret_cast<const float4*>(
                &A[(size_t)(m0 + m) * K + k0 + kg]);
            As[kg + 0][m] = v.x; As[kg + 1][m] = v.y;
            As[kg + 2][m] = v.z; As[kg + 3][m] = v.w;
        }
        // load W tile (64 x 16) transposed into Ws[k][n]
        {
            int n  = tid >> 2;
            int kg = (tid & 3) * 4;
            float4 v = *reinterpret_cast<const float4*>(
                &W[(size_t)(n0 + n) * K + k0 + kg]);
            Ws[kg + 0][n] = v.x; Ws[kg + 1][n] = v.y;
            Ws[kg + 2][n] = v.z; Ws[kg + 3][n] = v.w;
        }
        __syncthreads();

#pragma unroll
        for (int kk = 0; kk < 16; kk++) {
            float4 a0 = *reinterpret_cast<const float4*>(&As[kk][ty * 8]);
            float4 a1 = *reinterpret_cast<const float4*>(&As[kk][ty * 8 + 4]);
            float4 w  = *reinterpret_cast<const float4*>(&Ws[kk][tx * 4]);
            float am[8] = {a0.x, a0.y, a0.z, a0.w, a1.x, a1.y, a1.z, a1.w};
            float wn[4] = {w.x, w.y, w.z, w.w};
#pragma unroll
            for (int i = 0; i < 8; i++)
#pragma unroll
                for (int j = 0; j < 4; j++)
                    acc[i][j] = fmaf(am[i], wn[j], acc[i][j]);
        }
        __syncthreads();
    }

    // epilogue: channel = global_n / 4
    const int ch = (n0 >> 2) + tx;
    const float na = g_negA[LAYER * HID + ch];
#pragma unroll
    for (int i = 0; i < 8; i++) {
        int m = m0 + ty * 8 + i;
        float xs = acc[i][0];
        float Bv = acc[i][1];
        float Cv = acc[i][2];
        float dv = acc[i][3];
        float delta = 1.f / (1.f + expf(-dv));
        size_t o = (size_t)m * HID + ch;
        g_abar[o] = expf(delta * na);
        g_bx[o]   = Bv * xs;
        g_c[o]    = Cv;
    }
}

// ---------------- chunked scan ----------------
// pass1: per (chunk, channel): P = prod(a), S = scan with h0=0 (chunk end state)
__global__ void scan_pass1_kernel() {
    int h = threadIdx.x;
    int c = blockIdx.x;
    size_t base = (size_t)c * CHUNK * HID + h;
    float p = 1.f, s = 0.f;
#pragma unroll 8
    for (int i = 0; i < CHUNK; i++) {
        float a = g_abar[base + (size_t)i * HID];
        float b = g_bx  [base + (size_t)i * HID];
        p *= a;
        s = fmaf(a, s, b);
    }
    g_P[c * HID + h] = p;
    g_S[c * HID + h] = s;
}

// pass2: sequential scan over chunk carries; H0[c] = state at chunk start
__global__ void scan_pass2_kernel() {
    int h = threadIdx.x;
    float acc = 0.f;
#pragma unroll 4
    for (int c = 0; c < NCH; c++) {
        g_H0[c * HID + h] = acc;
        acc = fmaf(g_P[c * HID + h], acc, g_S[c * HID + h]);
    }
}

// pass3: replay recurrence with true chunk-start state, y = C * h
template <int LAYER>
__global__ void scan_pass3_kernel() {
    float* __restrict__ y = (LAYER == 0) ? g_y0 : g_y1;
    int h = threadIdx.x;
    int c = blockIdx.x;
    size_t base = (size_t)c * CHUNK * HID + h;
    float hs = g_H0[c * HID + h];
#pragma unroll 8
    for (int i = 0; i < CHUNK; i++) {
        size_t o = base + (size_t)i * HID;
        float a = g_abar[o];
        float b = g_bx[o];
        hs = fmaf(a, hs, b);
        y[o] = g_c[o] * hs;
    }
}

// ---------------- output head: softplus(y1 @ Wout.T + bout) + 1 ----------------
__global__ void head_kernel(const float* __restrict__ Wout,
                            const float* __restrict__ bout,
                            float* __restrict__ out) {
    __shared__ float ws[4 * HID];
    __shared__ float bs[4];
    int tid = threadIdx.x;
#pragma unroll
    for (int i = tid; i < 4 * HID; i += 256) ws[i] = Wout[i];
    if (tid < 4) bs[tid] = bout[tid];
    __syncthreads();

    int warp = tid >> 5, lane = tid & 31;
    int t = blockIdx.x * 8 + warp;
    float a0 = 0.f, a1 = 0.f, a2 = 0.f, a3 = 0.f;
#pragma unroll
    for (int j = 0; j < 8; j++) {
        int hh = lane + j * 32;
        float v = g_y1[(size_t)t * HID + hh];
        a0 = fmaf(v, ws[0 * HID + hh], a0);
        a1 = fmaf(v, ws[1 * HID + hh], a1);
        a2 = fmaf(v, ws[2 * HID + hh], a2);
        a3 = fmaf(v, ws[3 * HID + hh], a3);
    }
#pragma unroll
    for (int o = 16; o > 0; o >>= 1) {
        a0 += __shfl_down_sync(0xFFFFFFFFu, a0, o);
        a1 += __shfl_down_sync(0xFFFFFFFFu, a1, o);
        a2 += __shfl_down_sync(0xFFFFFFFFu, a2, o);
        a3 += __shfl_down_sync(0xFFFFFFFFu, a3, o);
    }
    if (lane == 0) {
        float z[4] = {a0 + bs[0], a1 + bs[1], a2 + bs[2], a3 + bs[3]};
#pragma unroll
        for (int o = 0; o < 4; o++) {
            float zz = z[o];
            float sp = (zz > 20.f) ? zz : log1pf(expf(zz));
            out[(size_t)t * 4 + o] = sp + 1.f;
        }
    }
}

// ---------------- launch ----------------
extern "C" void kernel_launch(void* const* d_in, const int* in_sizes, int n_in,
                              void* d_out, int out_size) {
    const float* obs   = (const float*)d_in[0];
    const int*   act   = (const int*)  d_in[1];
    const float* emb   = (const float*)d_in[2];
    const float* Win0  = (const float*)d_in[3];
    const float* WB0   = (const float*)d_in[4];
    const float* WC0   = (const float*)d_in[5];
    const float* Wd0   = (const float*)d_in[6];
    const float* Alog0 = (const float*)d_in[7];
    const float* Win1  = (const float*)d_in[8];
    const float* WB1   = (const float*)d_in[9];
    const float* WC1   = (const float*)d_in[10];
    const float* Wd1   = (const float*)d_in[11];
    const float* Alog1 = (const float*)d_in[12];
    const float* Wout  = (const float*)d_in[13];
    const float* bout  = (const float*)d_in[14];
    float* out = (float*)d_out;

    prep_w0_kernel<<<(NOUT * INP) / 256, 256>>>(Win0, WB0, WC0, Wd0);
    prep_w1_kernel<<<(NOUT * HID) / 256, 256>>>(Win1, WB1, WC1, Wd1);
    prep_a_kernel<<<1, 256>>>(Alog0, Alog1);
    build_x_kernel<<<(T_LEN * INP) / 256, 256>>>(obs, act, emb);

    dim3 ggrid(NOUT / 64, T_LEN / 128);

    // layer 0
    gemm_fused_kernel<0><<<ggrid, 256>>>();
    scan_pass1_kernel<<<NCH, HID>>>();
    scan_pass2_kernel<<<1, HID>>>();
    scan_pass3_kernel<0><<<NCH, HID>>>();

    // layer 1
    gemm_fused_kernel<1><<<ggrid, 256>>>();
    scan_pass1_kernel<<<NCH, HID>>>();
    scan_pass2_kernel<<<1, HID>>>();
    scan_pass3_kernel<1><<<NCH, HID>>>();

    // head
    head_kernel<<<T_LEN / 8, 256>>>(Wout, bout, out);
}

// round 3
// speedup vs baseline: 1.3952x; 1.3952x over previous
#include <cuda_runtime.h>
#include <cuda_bf16.h>
#include <math.h>
#include <stdint.h>

#define T_LEN   65536
#define HID     256
#define K0PAD   96          // layer-0 K (real 72) padded to 3x32
#define IN_RAW  72
#define NOUT    1024        // 4*HID interleaved weight rows
#define CHUNK   256
#define NCH     (T_LEN / CHUNK)

// ======================= scratch =======================
static __device__ __nv_bfloat16 g_Ah0[(size_t)T_LEN * K0PAD];
static __device__ __nv_bfloat16 g_Al0[(size_t)T_LEN * K0PAD];
static __device__ __nv_bfloat16 g_Ah1[(size_t)T_LEN * HID];
static __device__ __nv_bfloat16 g_Al1[(size_t)T_LEN * HID];
static __device__ __nv_bfloat16 g_Wh0[NOUT * K0PAD];
static __device__ __nv_bfloat16 g_Wl0[NOUT * K0PAD];
static __device__ __nv_bfloat16 g_Wh1[NOUT * HID];
static __device__ __nv_bfloat16 g_Wl1[NOUT * HID];
static __device__ float g_abar[(size_t)T_LEN * HID];
static __device__ float g_bx  [(size_t)T_LEN * HID];
static __device__ float g_c   [(size_t)T_LEN * HID];
static __device__ float g_y1  [(size_t)T_LEN * HID];
static __device__ float g_P   [NCH * HID];
static __device__ float g_S   [NCH * HID];
static __device__ float g_H0  [NCH * HID];
static __device__ float g_negA[2 * HID];

__device__ __forceinline__ void split_bf16(float v, __nv_bfloat16& hi, __nv_bfloat16& lo) {
    hi = __float2bfloat16(v);
    lo = __float2bfloat16(v - __bfloat162float(hi));
}

__device__ __forceinline__ uint32_t smem_u32(const void* p) {
    uint32_t a;
    asm("{ .reg .u64 t; cvta.to.shared.u64 t, %1; cvt.u32.u64 %0, t; }" : "=r"(a) : "l"(p));
    return a;
}

#define CP16(so, gp) \
    asm volatile("cp.async.cg.shared.global [%0], [%1], 16;" :: "r"(so), "l"(gp) : "memory")
#define CP_COMMIT() asm volatile("cp.async.commit_group;" ::: "memory")
#define CP_WAIT(n)  asm volatile("cp.async.wait_group %0;" :: "n"(n) : "memory")

#define LDSM4(r, addr) \
    asm volatile("ldmatrix.sync.aligned.m8n8.x4.shared.b16 {%0,%1,%2,%3}, [%4];" \
        : "=r"((r)[0]), "=r"((r)[1]), "=r"((r)[2]), "=r"((r)[3]) : "r"(addr))

#define MMA(d, a, b) \
    asm volatile("mma.sync.aligned.m16n8k16.row.col.f32.bf16.bf16.f32 " \
        "{%0,%1,%2,%3}, {%4,%5,%6,%7}, {%8,%9}, {%0,%1,%2,%3};" \
        : "+f"((d)[0]), "+f"((d)[1]), "+f"((d)[2]), "+f"((d)[3]) \
        : "r"((a)[0]), "r"((a)[1]), "r"((a)[2]), "r"((a)[3]), \
          "r"((b)[0]), "r"((b)[1]))

// ======================= prep =======================
__global__ void prep_w0_kernel(const float* __restrict__ Win, const float* __restrict__ WB,
                               const float* __restrict__ WC, const float* __restrict__ Wd) {
    int idx = blockIdx.x * 256 + threadIdx.x;          // NOUT*K0PAD
    int r = idx / K0PAD, k = idx % K0PAD;
    int h = r >> 2, j = r & 3;
    float v = 0.f;
    if (k < IN_RAW) {
        const float* s = (j == 0) ? Win : (j == 1) ? WB : (j == 2) ? WC : Wd;
        v = s[h * IN_RAW + k];
    }
    __nv_bfloat16 hi, lo; split_bf16(v, hi, lo);
    g_Wh0[idx] = hi; g_Wl0[idx] = lo;
}

__global__ void prep_w1_kernel(const float* __restrict__ Win, const float* __restrict__ WB,
                               const float* __restrict__ WC, const float* __restrict__ Wd) {
    int idx = blockIdx.x * 256 + threadIdx.x;          // NOUT*HID
    int r = idx / HID, k = idx % HID;
    int h = r >> 2, j = r & 3;
    const float* s = (j == 0) ? Win : (j == 1) ? WB : (j == 2) ? WC : Wd;
    __nv_bfloat16 hi, lo; split_bf16(s[h * HID + k], hi, lo);
    g_Wh1[idx] = hi; g_Wl1[idx] = lo;
}

__global__ void prep_a_kernel(const float* __restrict__ A0, const float* __restrict__ A1) {
    int h = threadIdx.x;
    g_negA[h] = -expf(A0[h]);
    g_negA[HID + h] = -expf(A1[h]);
}

__global__ void build_x_kernel(const float* __restrict__ obs, const int* __restrict__ act,
                               const float* __restrict__ emb) {
    int idx = blockIdx.x * 256 + threadIdx.x;          // T_LEN*K0PAD
    int t = idx / K0PAD, k = idx % K0PAD;
    float v = 0.f;
    if (k < 64)      v = obs[t * 64 + k];
    else if (k < 72) v = emb[act[t] * 8 + (k - 64)];
    __nv_bfloat16 hi, lo; split_bf16(v, hi, lo);
    g_Ah0[idx] = hi; g_Al0[idx] = lo;
}

// ======================= HMMA GEMM + gate epilogue =======================
// CTA: 128(M=T rows) x 128(N), BK=32 bf16, 2-stage cp.async pipeline,
// 3-term bf16 split accumulated in fp32: Ah*Wh + Ah*Wl + Al*Wh.
// SMEM stage: Ah|Al|Wh|Wl, each 128 rows x 32 bf16, row stride 80B (10240 B).
#define STAGE_BYTES 40960
#define SMEM_BYTES  (2 * STAGE_BYTES)   // also reused as 128x132 f32 epilogue stage (67584)

__device__ __forceinline__ void copy_tile(uint32_t sm, const __nv_bfloat16* g,
                                          int row0, int K, int k0, int tid) {
#pragma unroll
    for (int i = 0; i < 2; i++) {
        int idx = tid + i * 256;
        int row = idx >> 2, seg = idx & 3;
        CP16(sm + row * 80 + seg * 16,
             g + (size_t)(row0 + row) * K + k0 + seg * 8);
    }
}

template <int LAYER>
__global__ void __launch_bounds__(256, 1) gemm_mma_kernel() {
    constexpr int K = (LAYER == 0) ? K0PAD : HID;
    constexpr int NC = K / 32;
    const __nv_bfloat16* __restrict__ Ah = (LAYER == 0) ? g_Ah0 : g_Ah1;
    const __nv_bfloat16* __restrict__ Al = (LAYER == 0) ? g_Al0 : g_Al1;
    const __nv_bfloat16* __restrict__ Wh = (LAYER == 0) ? g_Wh0 : g_Wh1;
    const __nv_bfloat16* __restrict__ Wl = (LAYER == 0) ? g_Wl0 : g_Wl1;

    extern __shared__ __align__(16) char smem[];
    const uint32_t sb = smem_u32(smem);
    const int tid = threadIdx.x, lane = tid & 31;
    const int wm = (tid >> 5) >> 1, wn = (tid >> 5) & 1;
    const int m0 = blockIdx.y * 128, n0 = blockIdx.x * 128;
    const int q = lane >> 3, r = lane & 7;

    float acc[2][8][4];
#pragma unroll
    for (int mt = 0; mt < 2; mt++)
#pragma unroll
        for (int nt = 0; nt < 8; nt++)
#pragma unroll
            for (int i = 0; i < 4; i++) acc[mt][nt][i] = 0.f;

    // prologue: stage 0
    {
        uint32_t base = sb;
        copy_tile(base,         Ah, m0, K, 0, tid);
        copy_tile(base + 10240, Al, m0, K, 0, tid);
        copy_tile(base + 20480, Wh, n0, K, 0, tid);
        copy_tile(base + 30720, Wl, n0, K, 0, tid);
        CP_COMMIT();
    }

    for (int ck = 0; ck < NC; ck++) {
        if (ck + 1 < NC) {
            uint32_t base = sb + ((ck + 1) & 1) * STAGE_BYTES;
            int k0 = (ck + 1) * 32;
            copy_tile(base,         Ah, m0, K, k0, tid);
            copy_tile(base + 10240, Al, m0, K, k0, tid);
            copy_tile(base + 20480, Wh, n0, K, k0, tid);
            copy_tile(base + 30720, Wl, n0, K, k0, tid);
            CP_COMMIT();
            CP_WAIT(1);
        } else {
            CP_WAIT(0);
        }
        __syncthreads();

        const uint32_t base = sb + (ck & 1) * STAGE_BYTES;
#pragma unroll
        for (int ks = 0; ks < 2; ks++) {
            uint32_t ah[2][4], al[2][4];
#pragma unroll
            for (int mt = 0; mt < 2; mt++) {
                uint32_t rowA = wm * 32 + mt * 16 + (q & 1) * 8 + r;
                uint32_t addr = base + rowA * 80 + ks * 32 + (q >> 1) * 16;
                LDSM4(ah[mt], addr);
                LDSM4(al[mt], addr + 10240);
            }
            uint32_t wh[4][4], wl[4][4];
#pragma unroll
            for (int p = 0; p < 4; p++) {
                uint32_t rowW = wn * 64 + p * 16 + (q >> 1) * 8 + r;
                uint32_t addr = base + 20480 + rowW * 80 + ks * 32 + (q & 1) * 16;
                LDSM4(wh[p], addr);
                LDSM4(wl[p], addr + 10240);
            }
#pragma unroll
            for (int mt = 0; mt < 2; mt++)
#pragma unroll
                for (int nt = 0; nt < 8; nt++) {
                    const uint32_t* bh = &wh[nt >> 1][(nt & 1) * 2];
                    const uint32_t* bl = &wl[nt >> 1][(nt & 1) * 2];
                    MMA(acc[mt][nt], ah[mt], bh);
                    MMA(acc[mt][nt], ah[mt], bl);
                    MMA(acc[mt][nt], al[mt], bh);
                }
        }
        __syncthreads();
    }

    // ---- epilogue: acc -> SMEM stage (stride 132) -> gate math -> coalesced stores
    float* stage = (float*)smem;
#pragma unroll
    for (int mt = 0; mt < 2; mt++)
#pragma unroll
        for (int nt = 0; nt < 8; nt++) {
            int row = wm * 32 + mt * 16 + (lane >> 2);
            int col = wn * 64 + nt * 8 + (lane & 3) * 2;
            stage[row * 132 + col]           = acc[mt][nt][0];
            stage[row * 132 + col + 1]       = acc[mt][nt][1];
            stage[(row + 8) * 132 + col]     = acc[mt][nt][2];
            stage[(row + 8) * 132 + col + 1] = acc[mt][nt][3];
        }
    __syncthreads();

    const int chl = tid & 31;
    const int rb = tid >> 5;
    const int chg = blockIdx.x * 32 + chl;             // CTA covers 32 channels
    const float na = g_negA[LAYER * HID + chg];
#pragma unroll
    for (int i = 0; i < 16; i++) {
        int row = rb + i * 8;
        float4 v = *(const float4*)&stage[row * 132 + chl * 4];  // xs, B, C, d
        float delta = 1.f / (1.f + expf(-v.w));
        size_t o = (size_t)(m0 + row) * HID + chg;
        g_abar[o] = expf(delta * na);
        g_bx[o]   = v.y * v.x;
        g_c[o]    = v.z;
    }
}

// ======================= chunked scan =======================
__global__ void scan_pass1_kernel() {
    int h = threadIdx.x, c = blockIdx.x;
    size_t base = (size_t)c * CHUNK * HID + h;
    float p = 1.f, s = 0.f;
#pragma unroll 8
    for (int i = 0; i < CHUNK; i++) {
        float a = g_abar[base + (size_t)i * HID];
        float b = g_bx  [base + (size_t)i * HID];
        p *= a;
        s = fmaf(a, s, b);
    }
    g_P[c * HID + h] = p;
    g_S[c * HID + h] = s;
}

__global__ void scan_pass2_kernel() {
    int h = threadIdx.x;
    float acc = 0.f;
#pragma unroll 4
    for (int c = 0; c < NCH; c++) {
        g_H0[c * HID + h] = acc;
        acc = fmaf(g_P[c * HID + h], acc, g_S[c * HID + h]);
    }
}

// pass3: layer 0 emits bf16 hi/lo (next GEMM input); layer 1 emits fp32 for head
template <int LAYER>
__global__ void scan_pass3_kernel() {
    int h = threadIdx.x, c = blockIdx.x;
    size_t base = (size_t)c * CHUNK * HID + h;
    float hs = g_H0[c * HID + h];
#pragma unroll 8
    for (int i = 0; i < CHUNK; i++) {
        size_t o = base + (size_t)i * HID;
        hs = fmaf(g_abar[o], hs, g_bx[o]);
        float y = g_c[o] * hs;
        if (LAYER == 0) {
            __nv_bfloat16 hi, lo; split_bf16(y, hi, lo);
            g_Ah1[o] = hi; g_Al1[o] = lo;
        } else {
            g_y1[o] = y;
        }
    }
}

// ======================= output head =======================
__global__ void head_kernel(const float* __restrict__ Wout, const float* __restrict__ bout,
                            float* __restrict__ out) {
    __shared__ float ws[4 * HID];
    __shared__ float bs[4];
    int tid = threadIdx.x;
    for (int i = tid; i < 4 * HID; i += 256) ws[i] = Wout[i];
    if (tid < 4) bs[tid] = bout[tid];
    __syncthreads();

    int warp = tid >> 5, lane = tid & 31;
    int t = blockIdx.x * 8 + warp;
    float a0 = 0.f, a1 = 0.f, a2 = 0.f, a3 = 0.f;
#pragma unroll
    for (int j = 0; j < 8; j++) {
        int hh = lane + j * 32;
        float v = g_y1[(size_t)t * HID + hh];
        a0 = fmaf(v, ws[0 * HID + hh], a0);
        a1 = fmaf(v, ws[1 * HID + hh], a1);
        a2 = fmaf(v, ws[2 * HID + hh], a2);
        a3 = fmaf(v, ws[3 * HID + hh], a3);
    }
#pragma unroll
    for (int o = 16; o > 0; o >>= 1) {
        a0 += __shfl_down_sync(0xFFFFFFFFu, a0, o);
        a1 += __shfl_down_sync(0xFFFFFFFFu, a1, o);
        a2 += __shfl_down_sync(0xFFFFFFFFu, a2, o);
        a3 += __shfl_down_sync(0xFFFFFFFFu, a3, o);
    }
    if (lane == 0) {
        float z[4] = {a0 + bs[0], a1 + bs[1], a2 + bs[2], a3 + bs[3]};
#pragma unroll
        for (int o = 0; o < 4; o++) {
            float zz = z[o];
            float sp = (zz > 20.f) ? zz : log1pf(expf(zz));
            out[(size_t)t * 4 + o] = sp + 1.f;
        }
    }
}

// ======================= launch =======================
extern "C" void kernel_launch(void* const* d_in, const int* in_sizes, int n_in,
                              void* d_out, int out_size) {
    const float* obs   = (const float*)d_in[0];
    const int*   act   = (const int*)  d_in[1];
    const float* emb   = (const float*)d_in[2];
    const float* Win0  = (const float*)d_in[3];
    const float* WB0   = (const float*)d_in[4];
    const float* WC0   = (const float*)d_in[5];
    const float* Wd0   = (const float*)d_in[6];
    const float* Alog0 = (const float*)d_in[7];
    const float* Win1  = (const float*)d_in[8];
    const float* WB1   = (const float*)d_in[9];
    const float* WC1   = (const float*)d_in[10];
    const float* Wd1   = (const float*)d_in[11];
    const float* Alog1 = (const float*)d_in[12];
    const float* Wout  = (const float*)d_in[13];
    const float* bout  = (const float*)d_in[14];
    float* out = (float*)d_out;

    cudaFuncSetAttribute(gemm_mma_kernel<0>, cudaFuncAttributeMaxDynamicSharedMemorySize, SMEM_BYTES);
    cudaFuncSetAttribute(gemm_mma_kernel<1>, cudaFuncAttributeMaxDynamicSharedMemorySize, SMEM_BYTES);

    prep_w0_kernel<<<(NOUT * K0PAD) / 256, 256>>>(Win0, WB0, WC0, Wd0);
    prep_w1_kernel<<<(NOUT * HID) / 256, 256>>>(Win1, WB1, WC1, Wd1);
    prep_a_kernel<<<1, 256>>>(Alog0, Alog1);
    build_x_kernel<<<(T_LEN * K0PAD) / 256, 256>>>(obs, act, emb);

    dim3 ggrid(NOUT / 128, T_LEN / 128);   // (8, 512)

    gemm_mma_kernel<0><<<ggrid, 256, SMEM_BYTES>>>();
    scan_pass1_kernel<<<NCH, HID>>>();
    scan_pass2_kernel<<<1, HID>>>();
    scan_pass3_kernel<0><<<NCH, HID>>>();

    gemm_mma_kernel<1><<<ggrid, 256, SMEM_BYTES>>>();
    scan_pass1_kernel<<<NCH, HID>>>();
    scan_pass2_kernel<<<1, HID>>>();
    scan_pass3_kernel<1><<<NCH, HID>>>();

    head_kernel<<<T_LEN / 8, 256>>>(Wout, bout, out);
}

// round 4
// speedup vs baseline: 1.5755x; 1.1293x over previous
#include <cuda_runtime.h>
#include <cuda_bf16.h>
#include <math.h>
#include <stdint.h>

#define T_LEN   65536
#define HID     256
#define K0PAD   96          // layer-0 K (real 72) padded to 3x32
#define IN_RAW  72
#define NOUT    1024        // 4*HID interleaved weight rows
#define CHUNK   256
#define NCH     (T_LEN / CHUNK)

// ======================= scratch =======================
static __device__ __nv_bfloat16 g_Ah0[(size_t)T_LEN * K0PAD];
static __device__ __nv_bfloat16 g_Al0[(size_t)T_LEN * K0PAD];
static __device__ __nv_bfloat16 g_Ah1[(size_t)T_LEN * HID];
static __device__ __nv_bfloat16 g_Al1[(size_t)T_LEN * HID];
static __device__ __nv_bfloat16 g_Wh0[NOUT * K0PAD];
static __device__ __nv_bfloat16 g_Wl0[NOUT * K0PAD];
static __device__ __nv_bfloat16 g_Wh1[NOUT * HID];
static __device__ __nv_bfloat16 g_Wl1[NOUT * HID];
static __device__ float g_abar[(size_t)T_LEN * HID];
static __device__ float g_bx  [(size_t)T_LEN * HID];
static __device__ float g_c   [(size_t)T_LEN * HID];
static __device__ float g_y1  [(size_t)T_LEN * HID];
static __device__ float g_P   [NCH * HID];
static __device__ float g_S   [NCH * HID];
static __device__ float g_H0  [NCH * HID];
static __device__ float g_negA[2 * HID];

__device__ __forceinline__ void split_bf16(float v, __nv_bfloat16& hi, __nv_bfloat16& lo) {
    hi = __float2bfloat16(v);
    lo = __float2bfloat16(v - __bfloat162float(hi));
}

__device__ __forceinline__ uint32_t smem_u32(const void* p) {
    uint32_t a;
    asm("{ .reg .u64 t; cvta.to.shared.u64 t, %1; cvt.u32.u64 %0, t; }" : "=r"(a) : "l"(p));
    return a;
}

#define CP16(so, gp) \
    asm volatile("cp.async.cg.shared.global [%0], [%1], 16;" :: "r"(so), "l"(gp) : "memory")
#define CP_COMMIT() asm volatile("cp.async.commit_group;" ::: "memory")
#define CP_WAIT(n)  asm volatile("cp.async.wait_group %0;" :: "n"(n) : "memory")

#define LDSM4(r, addr) \
    asm volatile("ldmatrix.sync.aligned.m8n8.x4.shared.b16 {%0,%1,%2,%3}, [%4];" \
        : "=r"((r)[0]), "=r"((r)[1]), "=r"((r)[2]), "=r"((r)[3]) : "r"(addr))

// NOTE: non-volatile — pure register op, lets ptxas schedule/interleave MMAs.
#define MMA(d, a, b) \
    asm("mma.sync.aligned.m16n8k16.row.col.f32.bf16.bf16.f32 " \
        "{%0,%1,%2,%3}, {%4,%5,%6,%7}, {%8,%9}, {%0,%1,%2,%3};" \
        : "+f"((d)[0]), "+f"((d)[1]), "+f"((d)[2]), "+f"((d)[3]) \
        : "r"((a)[0]), "r"((a)[1]), "r"((a)[2]), "r"((a)[3]), \
          "r"((b)[0]), "r"((b)[1]))

// ======================= prep =======================
__global__ void prep_w0_kernel(const float* __restrict__ Win, const float* __restrict__ WB,
                               const float* __restrict__ WC, const float* __restrict__ Wd) {
    int idx = blockIdx.x * 256 + threadIdx.x;          // NOUT*K0PAD
    int r = idx / K0PAD, k = idx % K0PAD;
    int h = r >> 2, j = r & 3;
    float v = 0.f;
    if (k < IN_RAW) {
        const float* s = (j == 0) ? Win : (j == 1) ? WB : (j == 2) ? WC : Wd;
        v = s[h * IN_RAW + k];
    }
    __nv_bfloat16 hi, lo; split_bf16(v, hi, lo);
    g_Wh0[idx] = hi; g_Wl0[idx] = lo;
}

__global__ void prep_w1_kernel(const float* __restrict__ Win, const float* __restrict__ WB,
                               const float* __restrict__ WC, const float* __restrict__ Wd) {
    int idx = blockIdx.x * 256 + threadIdx.x;          // NOUT*HID
    int r = idx / HID, k = idx % HID;
    int h = r >> 2, j = r & 3;
    const float* s = (j == 0) ? Win : (j == 1) ? WB : (j == 2) ? WC : Wd;
    __nv_bfloat16 hi, lo; split_bf16(s[h * HID + k], hi, lo);
    g_Wh1[idx] = hi; g_Wl1[idx] = lo;
}

__global__ void prep_a_kernel(const float* __restrict__ A0, const float* __restrict__ A1) {
    int h = threadIdx.x;
    g_negA[h] = -expf(A0[h]);
    g_negA[HID + h] = -expf(A1[h]);
}

__global__ void build_x_kernel(const float* __restrict__ obs, const int* __restrict__ act,
                               const float* __restrict__ emb) {
    int idx = blockIdx.x * 256 + threadIdx.x;          // T_LEN*K0PAD
    int t = idx / K0PAD, k = idx % K0PAD;
    float v = 0.f;
    if (k < 64)      v = obs[t * 64 + k];
    else if (k < 72) v = emb[act[t] * 8 + (k - 64)];
    __nv_bfloat16 hi, lo; split_bf16(v, hi, lo);
    g_Ah0[idx] = hi; g_Al0[idx] = lo;
}

// ======================= HMMA GEMM + gate epilogue =======================
// CTA: 128(M) x 128(N), BK=32 bf16, 2-stage cp.async pipeline, 2 CTAs/SM.
// 3-term bf16 split in fp32: Ah*Wh + Ah*Wl + Al*Wh.
// SMEM stage: Ah|Al|Wh|Wl, 128 rows x 32 bf16 each, row stride 80B.
#define STAGE_BYTES 40960
#define SMEM_BYTES  (2 * STAGE_BYTES)   // reused as 128x132 f32 epilogue stage

__device__ __forceinline__ void copy_tile(uint32_t sm, const __nv_bfloat16* g,
                                          int row0, int K, int k0, int tid) {
#pragma unroll
    for (int i = 0; i < 2; i++) {
        int idx = tid + i * 256;
        int row = idx >> 2, seg = idx & 3;
        CP16(sm + row * 80 + seg * 16,
             g + (size_t)(row0 + row) * K + k0 + seg * 8);
    }
}

template <int LAYER>
__global__ void __launch_bounds__(256, 2) gemm_mma_kernel() {
    constexpr int K = (LAYER == 0) ? K0PAD : HID;
    constexpr int NC = K / 32;
    const __nv_bfloat16* __restrict__ Ah = (LAYER == 0) ? g_Ah0 : g_Ah1;
    const __nv_bfloat16* __restrict__ Al = (LAYER == 0) ? g_Al0 : g_Al1;
    const __nv_bfloat16* __restrict__ Wh = (LAYER == 0) ? g_Wh0 : g_Wh1;
    const __nv_bfloat16* __restrict__ Wl = (LAYER == 0) ? g_Wl0 : g_Wl1;

    extern __shared__ __align__(16) char smem[];
    const uint32_t sb = smem_u32(smem);
    const int tid = threadIdx.x, lane = tid & 31;
    const int wm = (tid >> 5) >> 1, wn = (tid >> 5) & 1;
    const int m0 = blockIdx.y * 128, n0 = blockIdx.x * 128;
    const int q = lane >> 3, r = lane & 7;

    // per-warp ldmatrix base offsets (constant across chunks)
    const uint32_t aoff = (uint32_t)(wm * 32 + (q & 1) * 8 + r) * 80 + (q >> 1) * 16;
    const uint32_t woff = 20480u + (uint32_t)(wn * 64 + (q >> 1) * 8 + r) * 80 + (q & 1) * 16;

    float acc[2][8][4];
#pragma unroll
    for (int mt = 0; mt < 2; mt++)
#pragma unroll
        for (int nt = 0; nt < 8; nt++)
#pragma unroll
            for (int i = 0; i < 4; i++) acc[mt][nt][i] = 0.f;

    // prologue: stage 0
    {
        copy_tile(sb,         Ah, m0, K, 0, tid);
        copy_tile(sb + 10240, Al, m0, K, 0, tid);
        copy_tile(sb + 20480, Wh, n0, K, 0, tid);
        copy_tile(sb + 30720, Wl, n0, K, 0, tid);
        CP_COMMIT();
    }

    for (int ck = 0; ck < NC; ck++) {
        if (ck + 1 < NC) {
            uint32_t base = sb + ((ck + 1) & 1) * STAGE_BYTES;
            int k0 = (ck + 1) * 32;
            copy_tile(base,         Ah, m0, K, k0, tid);
            copy_tile(base + 10240, Al, m0, K, k0, tid);
            copy_tile(base + 20480, Wh, n0, K, k0, tid);
            copy_tile(base + 30720, Wl, n0, K, k0, tid);
            CP_COMMIT();
            CP_WAIT(1);
        } else {
            CP_WAIT(0);
        }
        __syncthreads();

        const uint32_t base = sb + (ck & 1) * STAGE_BYTES;
#pragma unroll
        for (int ks = 0; ks < 2; ks++) {
            uint32_t ah[2][4], al[2][4];
#pragma unroll
            for (int mt = 0; mt < 2; mt++) {
                uint32_t addr = base + aoff + (uint32_t)mt * (16 * 80) + ks * 32;
                LDSM4(ah[mt], addr);
                LDSM4(al[mt], addr + 10240);
            }
#pragma unroll
            for (int p = 0; p < 4; p++) {
                uint32_t wh[4], wl[4];
                uint32_t addr = base + woff + (uint32_t)p * (16 * 80) + ks * 32;
                LDSM4(wh, addr);
                LDSM4(wl, addr + 10240);
                const int nt0 = p * 2, nt1 = p * 2 + 1;
                // 12 MMAs, grouped by term: reuse distance 4 between same-acc writes
                MMA(acc[0][nt0], ah[0], (wh + 0)); MMA(acc[0][nt1], ah[0], (wh + 2));
                MMA(acc[1][nt0], ah[1], (wh + 0)); MMA(acc[1][nt1], ah[1], (wh + 2));
                MMA(acc[0][nt0], ah[0], (wl + 0)); MMA(acc[0][nt1], ah[0], (wl + 2));
                MMA(acc[1][nt0], ah[1], (wl + 0)); MMA(acc[1][nt1], ah[1], (wl + 2));
                MMA(acc[0][nt0], al[0], (wh + 0)); MMA(acc[0][nt1], al[0], (wh + 2));
                MMA(acc[1][nt0], al[1], (wh + 0)); MMA(acc[1][nt1], al[1], (wh + 2));
            }
        }
        __syncthreads();
    }

    // ---- epilogue: acc -> SMEM stage (stride 132) -> gate math -> coalesced stores
    float* stage = (float*)smem;
#pragma unroll
    for (int mt = 0; mt < 2; mt++)
#pragma unroll
        for (int nt = 0; nt < 8; nt++) {
            int row = wm * 32 + mt * 16 + (lane >> 2);
            int col = wn * 64 + nt * 8 + (lane & 3) * 2;
            stage[row * 132 + col]           = acc[mt][nt][0];
            stage[row * 132 + col + 1]       = acc[mt][nt][1];
            stage[(row + 8) * 132 + col]     = acc[mt][nt][2];
            stage[(row + 8) * 132 + col + 1] = acc[mt][nt][3];
        }
    __syncthreads();

    const int chl = tid & 31;
    const int rb = tid >> 5;
    const int chg = blockIdx.x * 32 + chl;             // CTA covers 32 channels
    const float na = g_negA[LAYER * HID + chg];
#pragma unroll
    for (int i = 0; i < 16; i++) {
        int row = rb + i * 8;
        float4 v = *(const float4*)&stage[row * 132 + chl * 4];  // xs, B, C, d
        float delta = 1.f / (1.f + expf(-v.w));
        size_t o = (size_t)(m0 + row) * HID + chg;
        g_abar[o] = expf(delta * na);
        g_bx[o]   = v.y * v.x;
        g_c[o]    = v.z;
    }
}

// ======================= chunked scan =======================
__global__ void scan_pass1_kernel() {
    int h = threadIdx.x, c = blockIdx.x;
    size_t base = (size_t)c * CHUNK * HID + h;
    float p = 1.f, s = 0.f;
#pragma unroll 8
    for (int i = 0; i < CHUNK; i++) {
        float a = g_abar[base + (size_t)i * HID];
        float b = g_bx  [base + (size_t)i * HID];
        p *= a;
        s = fmaf(a, s, b);
    }
    g_P[c * HID + h] = p;
    g_S[c * HID + h] = s;
}

__global__ void scan_pass2_kernel() {
    int h = threadIdx.x;
    float acc = 0.f;
#pragma unroll 4
    for (int c = 0; c < NCH; c++) {
        g_H0[c * HID + h] = acc;
        acc = fmaf(g_P[c * HID + h], acc, g_S[c * HID + h]);
    }
}

// pass3: layer 0 emits bf16 hi/lo (next GEMM input); layer 1 emits fp32 for head
template <int LAYER>
__global__ void scan_pass3_kernel() {
    int h = threadIdx.x, c = blockIdx.x;
    size_t base = (size_t)c * CHUNK * HID + h;
    float hs = g_H0[c * HID + h];
#pragma unroll 8
    for (int i = 0; i < CHUNK; i++) {
        size_t o = base + (size_t)i * HID;
        hs = fmaf(g_abar[o], hs, g_bx[o]);
        float y = g_c[o] * hs;
        if (LAYER == 0) {
            __nv_bfloat16 hi, lo; split_bf16(y, hi, lo);
            g_Ah1[o] = hi; g_Al1[o] = lo;
        } else {
            g_y1[o] = y;
        }
    }
}

// ======================= output head =======================
__global__ void head_kernel(const float* __restrict__ Wout, const float* __restrict__ bout,
                            float* __restrict__ out) {
    __shared__ float ws[4 * HID];
    __shared__ float bs[4];
    int tid = threadIdx.x;
    for (int i = tid; i < 4 * HID; i += 256) ws[i] = Wout[i];
    if (tid < 4) bs[tid] = bout[tid];
    __syncthreads();

    int warp = tid >> 5, lane = tid & 31;
    int t = blockIdx.x * 8 + warp;
    float a0 = 0.f, a1 = 0.f, a2 = 0.f, a3 = 0.f;
#pragma unroll
    for (int j = 0; j < 8; j++) {
        int hh = lane + j * 32;
        float v = g_y1[(size_t)t * HID + hh];
        a0 = fmaf(v, ws[0 * HID + hh], a0);
        a1 = fmaf(v, ws[1 * HID + hh], a1);
        a2 = fmaf(v, ws[2 * HID + hh], a2);
        a3 = fmaf(v, ws[3 * HID + hh], a3);
    }
#pragma unroll
    for (int o = 16; o > 0; o >>= 1) {
        a0 += __shfl_down_sync(0xFFFFFFFFu, a0, o);
        a1 += __shfl_down_sync(0xFFFFFFFFu, a1, o);
        a2 += __shfl_down_sync(0xFFFFFFFFu, a2, o);
        a3 += __shfl_down_sync(0xFFFFFFFFu, a3, o);
    }
    if (lane == 0) {
        float z[4] = {a0 + bs[0], a1 + bs[1], a2 + bs[2], a3 + bs[3]};
#pragma unroll
        for (int o = 0; o < 4; o++) {
            float zz = z[o];
            float sp = (zz > 20.f) ? zz : log1pf(expf(zz));
            out[(size_t)t * 4 + o] = sp + 1.f;
        }
    }
}

// ======================= launch =======================
extern "C" void kernel_launch(void* const* d_in, const int* in_sizes, int n_in,
                              void* d_out, int out_size) {
    const float* obs   = (const float*)d_in[0];
    const int*   act   = (const int*)  d_in[1];
    const float* emb   = (const float*)d_in[2];
    const float* Win0  = (const float*)d_in[3];
    const float* WB0   = (const float*)d_in[4];
    const float* WC0   = (const float*)d_in[5];
    const float* Wd0   = (const float*)d_in[6];
    const float* Alog0 = (const float*)d_in[7];
    const float* Win1  = (const float*)d_in[8];
    const float* WB1   = (const float*)d_in[9];
    const float* WC1   = (const float*)d_in[10];
    const float* Wd1   = (const float*)d_in[11];
    const float* Alog1 = (const float*)d_in[12];
    const float* Wout  = (const float*)d_in[13];
    const float* bout  = (const float*)d_in[14];
    float* out = (float*)d_out;

    cudaFuncSetAttribute(gemm_mma_kernel<0>, cudaFuncAttributeMaxDynamicSharedMemorySize, SMEM_BYTES);
    cudaFuncSetAttribute(gemm_mma_kernel<1>, cudaFuncAttributeMaxDynamicSharedMemorySize, SMEM_BYTES);

    prep_w0_kernel<<<(NOUT * K0PAD) / 256, 256>>>(Win0, WB0, WC0, Wd0);
    prep_w1_kernel<<<(NOUT * HID) / 256, 256>>>(Win1, WB1, WC1, Wd1);
    prep_a_kernel<<<1, 256>>>(Alog0, Alog1);
    build_x_kernel<<<(T_LEN * K0PAD) / 256, 256>>>(obs, act, emb);

    dim3 ggrid(NOUT / 128, T_LEN / 128);   // (8, 512)

    gemm_mma_kernel<0><<<ggrid, 256, SMEM_BYTES>>>();
    scan_pass1_kernel<<<NCH, HID>>>();
    scan_pass2_kernel<<<1, HID>>>();
    scan_pass3_kernel<0><<<NCH, HID>>>();

    gemm_mma_kernel<1><<<ggrid, 256, SMEM_BYTES>>>();
    scan_pass1_kernel<<<NCH, HID>>>();
    scan_pass2_kernel<<<1, HID>>>();
    scan_pass3_kernel<1><<<NCH, HID>>>();

    head_kernel<<<T_LEN / 8, 256>>>(Wout, bout, out);
}